// round 10
// baseline (speedup 1.0000x reference)
#include <cuda_runtime.h>
#include <math.h>

#define NBATCH 4
#define NATOM  512
#define NSYM   4
#define NLAB   16
#define C1     32
#define C2     64
#define NTHR   128
#define GA     2          // atoms per iteration
#define ITER   2          // iterations per CTA (4 atoms total)
#define MAXNB  96
#define C0P    36         // padded centres0 row (floats)
#define C1P    68         // padded centres1 / LmT row (floats)
#define SQK    1.2011224087864498f   // sqrt(log2(e))

__constant__ int   c_pf[16] = {0,0,0,0,1,1,1,2,2,3, 0,0,0,0,0,0};
__constant__ int   c_ph[16] = {0,1,2,3,1,2,3,2,3,3, 0,0,0,0,0,0};
__constant__ float c_pw[16] = {1,2,2,2,1,2,2,1,2,1, 0,0,0,0,0,0};

__device__ __forceinline__ float ex2(float x) {
    float r; asm("ex2.approx.ftz.f32 %0, %1;" : "=f"(r) : "f"(x)); return r;
}

__global__ __launch_bounds__(NTHR)
void descriptor_kernel(const int*   __restrict__ numbers,
                       const float* __restrict__ coords,
                       const float* __restrict__ nuww0,
                       const float* __restrict__ sigmas0,
                       const float* __restrict__ centres0,
                       const float* __restrict__ nuww1,
                       const float* __restrict__ sigmas1,
                       const float* __restrict__ centres1,
                       float*       __restrict__ out)
{
    __shared__ float4 s_pos[NATOM];                  // 8 KB
    __shared__ float  s_c0s[NLAB * C0P];             // 2.25 KB (c0*s0*SQK, padded)
    __shared__ float  s_sc1[NLAB * C1P];             // 4.25 KB (c1*s1*SQK, padded)
    __shared__ float  s_w0[NLAB], s_s0f[NLAB], s_w1[NLAB], s_s1f[NLAB];
    __shared__ float4 nb_f4[GA][MAXNB];              // 3 KB
    __shared__ float2 nb_meta[GA][MAXNB];            // 1.5 KB (rs*s1*SQK, row offset)
    __shared__ int    s_lab[GA][MAXNB];              // 0.75 KB
    __shared__ float  LmT [GA][4][C1P];              // 2.13 KB
    __shared__ float  LmTs[GA][4][C1P];              // 2.13 KB (rf-scaled copy)
    __shared__ int    s_wcnt[GA][2];

    const int tid  = threadIdx.x;
    const int bidx = blockIdx.x;
    const int b    = bidx >> 7;                      // 128 CTAs per batch
    const int lane = tid & 31;
    const int warp = tid >> 5;
    const int g    = tid >> 6;                       // atom served (0/1)
    const int t64  = tid & 63;

    // ---- one-time setup: coords + folded tables ----
    {
        const float* cb  = coords  + (size_t)b * NATOM * 3;
        const int*   nbp = numbers + (size_t)b * NATOM;
        for (int t = tid; t < NATOM; t += NTHR)
            s_pos[t] = make_float4(cb[t * 3 + 0], cb[t * 3 + 1], cb[t * 3 + 2],
                                   __int_as_float(nbp[t]));
        for (int t = tid; t < NLAB * C1; t += NTHR) {
            const int lab = t >> 5, c = t & 31;
            s_c0s[lab * C0P + c] = centres0[t] * sigmas0[lab] * SQK;
        }
        for (int t = tid; t < NLAB * C2; t += NTHR) {
            const int lab = t >> 6, c = t & 63;
            s_sc1[lab * C1P + c] = centres1[t] * sigmas1[lab] * SQK;
        }
        if (tid < NLAB) {
            s_w0[tid]  = nuww0[tid];  s_s0f[tid] = sigmas0[tid] * SQK;
            s_w1[tid]  = nuww1[tid];  s_s1f[tid] = sigmas1[tid] * SQK;
        }
    }
    __syncthreads();

    for (int it2 = 0; it2 < ITER; it2++) {
        const int li0 = (bidx & 127) * (GA * ITER) + it2 * GA;

        // ---- Phase 1a: ballot compaction (2 warps/atom, 8 chunks each) ----
        {
            const int ww = (tid >> 5) & 1;
            const int il = li0 + g;
            const float4 ci = s_pos[il];
            const float xi = ci.x, yi = ci.y, zi = ci.z;

            unsigned mk[8];
            int cnt = 0;
            #pragma unroll
            for (int c = 0; c < 8; c++) {
                const int j = ww * 256 + c * 32 + lane;
                const float4 p = s_pos[j];
                const float dx = p.x - xi, dy = p.y - yi, dz = p.z - zi;
                const float d2 = dx * dx + dy * dy + dz * dz;
                const bool f = (j != il) && (d2 <= 36.0f);
                mk[c] = __ballot_sync(0xffffffffu, f);
                cnt += __popc(mk[c]);
            }
            if (lane == 0) s_wcnt[g][ww] = cnt;
            __syncthreads();   // also fences prior iteration's reads of nb_* / LmT*

            int base = (ww == 1) ? s_wcnt[g][0] : 0;
            const unsigned ltmask = (1u << lane) - 1u;
            const int zbase = __float_as_int(ci.w) * NSYM;
            #pragma unroll
            for (int c = 0; c < 8; c++) {
                if ((mk[c] >> lane) & 1u) {
                    const int pos = base + __popc(mk[c] & ltmask);
                    if (pos < MAXNB) {
                        const int j = ww * 256 + c * 32 + lane;
                        const float4 p = s_pos[j];
                        const float dx = p.x - xi, dy = p.y - yi, dz = p.z - zi;
                        const float d2 = dx * dx + dy * dy + dz * dz;
                        const float rinv = (d2 > 0.0f) ? rsqrtf(d2) : 0.0f;
                        const float d    = d2 * rinv;
                        const float fc   = 0.5f * __cosf(d * 0.52359877559829887f) + 0.5f;
                        const float gg   = rinv * fc;
                        nb_f4[g][pos] = make_float4(fc, dx * gg, dy * gg, dz * gg);
                        s_lab[g][pos] = zbase + __float_as_int(p.w);
                    }
                }
                base += __popc(mk[c]);
            }
        }
        __syncthreads();

        const int nnb = min(s_wcnt[g][0] + s_wcnt[g][1], MAXNB);

        // ---- Phase 1b: first RConv (8 thr/pair, 8 pairs/sweep/atom) ----
        {
            const int sub  = t64 & 7;
            const int slot = t64 >> 3;               // 0..7
            const int nIter = (nnb + 7) >> 3;        // warp-uniform (same g per warp)
            for (int it = 0; it < nIter; it++) {
                const int p  = slot + (it << 3);
                const int pc = (p < nnb) ? p : (nnb - 1);
                const int   lab = s_lab[g][pc];
                const float fc  = nb_f4[g][pc].x;
                const float fcs = fc * s_s0f[lab];
                const float4 c4 = *reinterpret_cast<const float4*>(&s_c0s[lab * C0P + sub * 4]);
                const float a0 = fcs - c4.x, a1 = fcs - c4.y, a2 = fcs - c4.z, a3 = fcs - c4.w;
                float sum = ex2(-a0 * a0) + ex2(-a1 * a1) + ex2(-a2 * a2) + ex2(-a3 * a3);
                sum += __shfl_xor_sync(0xffffffffu, sum, 1);
                sum += __shfl_xor_sync(0xffffffffu, sum, 2);
                sum += __shfl_xor_sync(0xffffffffu, sum, 4);
                if (sub == 0 && p < nnb) {
                    const float rs = s_w0[lab] * sum;
                    const float w1 = s_w1[lab];
                    nb_meta[g][p] = make_float2(rs * s_s1f[lab],
                                                __int_as_float(lab * C1P));
                    float4 f = nb_f4[g][p];
                    f.x *= w1; f.y *= w1; f.z *= w1; f.w *= w1;
                    nb_f4[g][p] = f;
                }
            }
        }
        __syncthreads();

        // ---- Phase 2: second RConv + Lm. 4 c2 x 4 neighbor-slices per thread ----
        {
            const int lw    = t64 >> 5;
            const int l5    = t64 & 31;
            const int grp   = l5 >> 2;
            const int slice = l5 & 3;
            const int c2b   = (lw * 8 + grp) * 4;

            float acc[4][4];
            #pragma unroll
            for (int a = 0; a < 4; a++)
                #pragma unroll
                for (int f = 0; f < 4; f++) acc[a][f] = 0.0f;

            for (int k = slice; k < nnb; k += 4) {
                const float2 m = nb_meta[g][k];
                const float4 cc = *reinterpret_cast<const float4*>(
                    &s_sc1[__float_as_int(m.y) + c2b]);
                const float t0 = m.x - cc.x, t1 = m.x - cc.y;
                const float t2 = m.x - cc.z, t3 = m.x - cc.w;
                const float p0 = ex2(-t0 * t0), p1 = ex2(-t1 * t1);
                const float p2 = ex2(-t2 * t2), p3 = ex2(-t3 * t3);
                const float4 f = nb_f4[g][k];
                acc[0][0] = fmaf(p0, f.x, acc[0][0]); acc[0][1] = fmaf(p0, f.y, acc[0][1]);
                acc[0][2] = fmaf(p0, f.z, acc[0][2]); acc[0][3] = fmaf(p0, f.w, acc[0][3]);
                acc[1][0] = fmaf(p1, f.x, acc[1][0]); acc[1][1] = fmaf(p1, f.y, acc[1][1]);
                acc[1][2] = fmaf(p1, f.z, acc[1][2]); acc[1][3] = fmaf(p1, f.w, acc[1][3]);
                acc[2][0] = fmaf(p2, f.x, acc[2][0]); acc[2][1] = fmaf(p2, f.y, acc[2][1]);
                acc[2][2] = fmaf(p2, f.z, acc[2][2]); acc[2][3] = fmaf(p2, f.w, acc[2][3]);
                acc[3][0] = fmaf(p3, f.x, acc[3][0]); acc[3][1] = fmaf(p3, f.y, acc[3][1]);
                acc[3][2] = fmaf(p3, f.z, acc[3][2]); acc[3][3] = fmaf(p3, f.w, acc[3][3]);
            }
            #pragma unroll
            for (int a = 0; a < 4; a++)
                #pragma unroll
                for (int f = 0; f < 4; f++) {
                    float v = acc[a][f];
                    v += __shfl_xor_sync(0xffffffffu, v, 1);
                    v += __shfl_xor_sync(0xffffffffu, v, 2);
                    acc[a][f] = v;
                }
            if (slice == 0) {
                #pragma unroll
                for (int f = 0; f < 4; f++)
                    *reinterpret_cast<float4*>(&LmT[g][f][c2b]) =
                        make_float4(acc[0][f], acc[1][f], acc[2][f], acc[3][f]);
            }
        }
        __syncthreads();

        // ---- Warp-per-atom epilogue: Gram -> rf -> scaled copy, all in-warp ----
        if (warp < GA) {
            const int g2   = warp;
            const int p    = lane >> 1;              // 0..15
            const int part = lane & 1;
            const int pc   = (p < 10) ? p : 9;
            const float4* rf4 = reinterpret_cast<const float4*>(&LmT[g2][c_pf[pc]][part * 32]);
            const float4* rh4 = reinterpret_cast<const float4*>(&LmT[g2][c_ph[pc]][part * 32]);
            float s = 0.0f;
            #pragma unroll
            for (int q = 0; q < 8; q++) {
                const float4 x = rf4[q], y = rh4[q];
                s = fmaf(x.x, y.x, s); s = fmaf(x.y, y.y, s);
                s = fmaf(x.z, y.z, s); s = fmaf(x.w, y.w, s);
            }
            s += __shfl_xor_sync(0xffffffffu, s, 1); // combine halves -> G_pc
            const float wq = (p < 10 && part == 0) ? c_pw[pc] : 0.0f;
            float tot = wq * s * s;
            tot += __shfl_xor_sync(0xffffffffu, tot, 1);
            tot += __shfl_xor_sync(0xffffffffu, tot, 2);
            tot += __shfl_xor_sync(0xffffffffu, tot, 4);
            tot += __shfl_xor_sync(0xffffffffu, tot, 8);
            tot += __shfl_xor_sync(0xffffffffu, tot, 16);
            const float rfv = rsqrtf(tot);
            const int base = lane * 8;
            const int ffb = base >> 6, ccb = base & 63;
            float4 v0 = *reinterpret_cast<const float4*>(&LmT[g2][ffb][ccb]);
            float4 v1 = *reinterpret_cast<const float4*>(&LmT[g2][ffb][ccb + 4]);
            v0.x *= rfv; v0.y *= rfv; v0.z *= rfv; v0.w *= rfv;
            v1.x *= rfv; v1.y *= rfv; v1.z *= rfv; v1.w *= rfv;
            *reinterpret_cast<float4*>(&LmTs[g2][ffb][ccb])     = v0;
            *reinterpret_cast<float4*>(&LmTs[g2][ffb][ccb + 4]) = v1;
        }
        __syncthreads();

        // ---- Phase 3: R = Lm (rf*Lm)^T; 8 float4 stores per thread per atom ----
        const int dd0 = (tid * 4) & 63;
        const int crw = tid >> 4;                    // 0..7
        #pragma unroll
        for (int g2 = 0; g2 < GA; g2++) {
            const float4 b0 = *reinterpret_cast<const float4*>(&LmTs[g2][0][dd0]);
            const float4 b1 = *reinterpret_cast<const float4*>(&LmTs[g2][1][dd0]);
            const float4 b2 = *reinterpret_cast<const float4*>(&LmTs[g2][2][dd0]);
            const float4 b3 = *reinterpret_cast<const float4*>(&LmTs[g2][3][dd0]);
            float* ob = out + ((size_t)(b * NATOM + li0 + g2) << 12);
            #pragma unroll
            for (int grp = 0; grp < 8; grp++) {
                const int c = grp * 8 + crw;
                const float a0 = LmT[g2][0][c], a1 = LmT[g2][1][c];
                const float a2 = LmT[g2][2][c], a3 = LmT[g2][3][c];
                float4 st;
                st.x = fmaf(a3, b3.x, fmaf(a2, b2.x, fmaf(a1, b1.x, a0 * b0.x)));
                st.y = fmaf(a3, b3.y, fmaf(a2, b2.y, fmaf(a1, b1.y, a0 * b0.y)));
                st.z = fmaf(a3, b3.z, fmaf(a2, b2.z, fmaf(a1, b1.z, a0 * b0.z)));
                st.w = fmaf(a3, b3.w, fmaf(a2, b2.w, fmaf(a1, b1.w, a0 * b0.w)));
                *reinterpret_cast<float4*>(ob + (grp << 9) + tid * 4) = st;
            }
        }
        // loop: next iteration's first barrier (in phase 1a) fences reuse of
        // nb_f4/nb_meta/LmT/LmTs before they are overwritten.
    }
}

extern "C" void kernel_launch(void* const* d_in, const int* in_sizes, int n_in,
                              void* d_out, int out_size)
{
    // metadata order: boxs, numbers, coords, nuww0, sigmas0, centres0, nuww1, sigmas1, centres1
    const int*   numbers  = (const int*)  d_in[1];
    const float* coords   = (const float*)d_in[2];
    const float* nuww0    = (const float*)d_in[3];
    const float* sigmas0  = (const float*)d_in[4];
    const float* centres0 = (const float*)d_in[5];
    const float* nuww1    = (const float*)d_in[6];
    const float* sigmas1  = (const float*)d_in[7];
    const float* centres1 = (const float*)d_in[8];
    float* out = (float*)d_out;

    descriptor_kernel<<<(NBATCH * NATOM) / (GA * ITER), NTHR>>>(
        numbers, coords, nuww0, sigmas0, centres0, nuww1, sigmas1, centres1, out);
}

// round 11
// speedup vs baseline: 1.1569x; 1.1569x over previous
#include <cuda_runtime.h>
#include <math.h>

#define NBATCH 4
#define NATOM  512
#define NSYM   4
#define NLAB   16
#define C1     32
#define C2     64
#define NTHR   128
#define GA     2          // atoms per CTA
#define MAXNB  96
#define C0P    36         // padded centres0 row (floats); 36*4B=144B, 16B-aligned rows
#define C1P    68         // padded centres1 / LmT row (floats)
#define SQK    1.2011224087864498f   // sqrt(log2(e))

__constant__ int   c_pf[16] = {0,0,0,0,1,1,1,2,2,3, 0,0,0,0,0,0};
__constant__ int   c_ph[16] = {0,1,2,3,1,2,3,2,3,3, 0,0,0,0,0,0};
__constant__ float c_pw[16] = {1,2,2,2,1,2,2,1,2,1, 0,0,0,0,0,0};

__device__ __forceinline__ float ex2(float x) {
    float r; asm("ex2.approx.ftz.f32 %0, %1;" : "=f"(r) : "f"(x)); return r;
}

__global__ __launch_bounds__(NTHR)
void descriptor_kernel(const int*   __restrict__ numbers,
                       const float* __restrict__ coords,
                       const float* __restrict__ nuww0,
                       const float* __restrict__ sigmas0,
                       const float* __restrict__ centres0,
                       const float* __restrict__ nuww1,
                       const float* __restrict__ sigmas1,
                       const float* __restrict__ centres1,
                       float*       __restrict__ out)
{
    __shared__ float4 s_pos[NATOM];                  // 8 KB
    __shared__ float  s_c0s[NLAB * C0P];             // 2.25 KB (c0*s0*SQK, padded)
    __shared__ float  s_sc1[NLAB * C1P];             // 4.25 KB (c1*s1*SQK, padded)
    __shared__ float  s_w0[NLAB], s_s0f[NLAB], s_w1[NLAB], s_s1f[NLAB];
    __shared__ float4 nb_f4[GA][MAXNB];              // 3 KB
    __shared__ float2 nb_meta[GA][MAXNB];            // 1.5 KB (rs*s1*SQK, row offset)
    __shared__ int    s_lab[GA][MAXNB];              // 0.75 KB
    __shared__ float  LmT [GA][4][C1P];              // 2.13 KB
    __shared__ float  LmTs[GA][4][C1P];              // 2.13 KB (rf-scaled copy)
    __shared__ int    s_wcnt[GA][4];

    const int tid  = threadIdx.x;
    const int bidx = blockIdx.x;
    const int b    = bidx >> 8;                      // 256 CTAs per batch
    const int li0  = (bidx & 255) * GA;
    const int lane = tid & 31;
    const int warp = tid >> 5;
    const int g    = tid >> 6;                       // atom served (0/1) in later phases
    const int t64  = tid & 63;

    // ---- cooperative loads + folded table pre-scaling ----
    {
        const float* cb  = coords  + (size_t)b * NATOM * 3;
        const int*   nbp = numbers + (size_t)b * NATOM;
        for (int t = tid; t < NATOM; t += NTHR)
            s_pos[t] = make_float4(cb[t * 3 + 0], cb[t * 3 + 1], cb[t * 3 + 2],
                                   __int_as_float(nbp[t]));
        for (int t = tid; t < NLAB * C1; t += NTHR) {
            const int lab = t >> 5, c = t & 31;
            s_c0s[lab * C0P + c] = centres0[t] * sigmas0[lab] * SQK;
        }
        for (int t = tid; t < NLAB * C2; t += NTHR) {
            const int lab = t >> 6, c = t & 63;
            s_sc1[lab * C1P + c] = centres1[t] * sigmas1[lab] * SQK;
        }
        if (tid < NLAB) {
            s_w0[tid]  = nuww0[tid];  s_s0f[tid] = sigmas0[tid] * SQK;
            s_w1[tid]  = nuww1[tid];  s_s1f[tid] = sigmas1[tid] * SQK;
        }
    }
    __syncthreads();

    // ---- Phase 1a: shared-j compaction. Warp w owns j in [w*128, w*128+128),
    //      tests BOTH atoms from one position load per candidate. ----
    {
        const float4 ci0 = s_pos[li0];
        const float4 ci1 = s_pos[li0 + 1];
        const int zb0 = __float_as_int(ci0.w) * NSYM;
        const int zb1 = __float_as_int(ci1.w) * NSYM;

        unsigned mk0[4], mk1[4];
        int cnt0 = 0, cnt1 = 0;
        #pragma unroll
        for (int c = 0; c < 4; c++) {
            const int j = warp * 128 + c * 32 + lane;
            const float4 p = s_pos[j];
            const float dx0 = p.x - ci0.x, dy0 = p.y - ci0.y, dz0 = p.z - ci0.z;
            const float dx1 = p.x - ci1.x, dy1 = p.y - ci1.y, dz1 = p.z - ci1.z;
            const float d20 = dx0 * dx0 + dy0 * dy0 + dz0 * dz0;
            const float d21 = dx1 * dx1 + dy1 * dy1 + dz1 * dz1;
            const bool f0 = (j != li0)     && (d20 <= 36.0f);
            const bool f1 = (j != li0 + 1) && (d21 <= 36.0f);
            mk0[c] = __ballot_sync(0xffffffffu, f0);
            mk1[c] = __ballot_sync(0xffffffffu, f1);
            cnt0 += __popc(mk0[c]);
            cnt1 += __popc(mk1[c]);
        }
        if (lane == 0) { s_wcnt[0][warp] = cnt0; s_wcnt[1][warp] = cnt1; }
        __syncthreads();

        int base0 = 0, base1 = 0;
        #pragma unroll
        for (int w = 0; w < 4; w++) {
            if (w < warp) { base0 += s_wcnt[0][w]; base1 += s_wcnt[1][w]; }
        }
        const unsigned ltmask = (1u << lane) - 1u;
        #pragma unroll
        for (int c = 0; c < 4; c++) {
            const int j = warp * 128 + c * 32 + lane;
            if ((mk0[c] >> lane) & 1u) {
                const int pos = base0 + __popc(mk0[c] & ltmask);
                if (pos < MAXNB) {
                    const float4 p = s_pos[j];
                    const float dx = p.x - ci0.x, dy = p.y - ci0.y, dz = p.z - ci0.z;
                    const float d2 = dx * dx + dy * dy + dz * dz;
                    const float rinv = (d2 > 0.0f) ? rsqrtf(d2) : 0.0f;
                    const float d    = d2 * rinv;
                    const float fc   = 0.5f * __cosf(d * 0.52359877559829887f) + 0.5f;
                    const float gg   = rinv * fc;
                    nb_f4[0][pos] = make_float4(fc, dx * gg, dy * gg, dz * gg);
                    s_lab[0][pos] = zb0 + __float_as_int(p.w);
                }
            }
            base0 += __popc(mk0[c]);
            if ((mk1[c] >> lane) & 1u) {
                const int pos = base1 + __popc(mk1[c] & ltmask);
                if (pos < MAXNB) {
                    const float4 p = s_pos[j];
                    const float dx = p.x - ci1.x, dy = p.y - ci1.y, dz = p.z - ci1.z;
                    const float d2 = dx * dx + dy * dy + dz * dz;
                    const float rinv = (d2 > 0.0f) ? rsqrtf(d2) : 0.0f;
                    const float d    = d2 * rinv;
                    const float fc   = 0.5f * __cosf(d * 0.52359877559829887f) + 0.5f;
                    const float gg   = rinv * fc;
                    nb_f4[1][pos] = make_float4(fc, dx * gg, dy * gg, dz * gg);
                    s_lab[1][pos] = zb1 + __float_as_int(p.w);
                }
            }
            base1 += __popc(mk1[c]);
        }
    }
    __syncthreads();

    const int nnb = min(s_wcnt[g][0] + s_wcnt[g][1] +
                        s_wcnt[g][2] + s_wcnt[g][3], MAXNB);

    // ---- Phase 1b: first RConv (4 thr/pair, 8 channels each, 16 pairs/sweep) ----
    {
        const int sub  = t64 & 3;                    // channel group of 8
        const int slot = t64 >> 2;                   // 0..15
        const int nIter = (nnb + 15) >> 4;           // warp-uniform (same g per warp)
        for (int it = 0; it < nIter; it++) {
            const int p  = slot + (it << 4);
            const int pc = (p < nnb) ? p : (nnb - 1);
            const int   lab = s_lab[g][pc];
            const float fc  = nb_f4[g][pc].x;
            const float fcs = fc * s_s0f[lab];
            const float4 cA = *reinterpret_cast<const float4*>(&s_c0s[lab * C0P + sub * 8]);
            const float4 cB = *reinterpret_cast<const float4*>(&s_c0s[lab * C0P + sub * 8 + 4]);
            const float a0 = fcs - cA.x, a1 = fcs - cA.y, a2 = fcs - cA.z, a3 = fcs - cA.w;
            const float a4 = fcs - cB.x, a5 = fcs - cB.y, a6 = fcs - cB.z, a7 = fcs - cB.w;
            float sum = ex2(-a0 * a0) + ex2(-a1 * a1) + ex2(-a2 * a2) + ex2(-a3 * a3)
                      + ex2(-a4 * a4) + ex2(-a5 * a5) + ex2(-a6 * a6) + ex2(-a7 * a7);
            sum += __shfl_xor_sync(0xffffffffu, sum, 1);
            sum += __shfl_xor_sync(0xffffffffu, sum, 2);
            if (sub == 0 && p < nnb) {
                const float rs = s_w0[lab] * sum;
                const float w1 = s_w1[lab];
                nb_meta[g][p] = make_float2(rs * s_s1f[lab],
                                            __int_as_float(lab * C1P));
                float4 f = nb_f4[g][p];
                f.x *= w1; f.y *= w1; f.z *= w1; f.w *= w1;
                nb_f4[g][p] = f;
            }
        }
    }
    __syncthreads();

    // ---- Phase 2: second RConv + Lm. 4 c2 x 4 neighbor-slices, k-unrolled x2 ----
    {
        const int lw    = t64 >> 5;
        const int l5    = t64 & 31;
        const int grp   = l5 >> 2;
        const int slice = l5 & 3;
        const int c2b   = (lw * 8 + grp) * 4;

        float acc[4][4];
        #pragma unroll
        for (int a = 0; a < 4; a++)
            #pragma unroll
            for (int f = 0; f < 4; f++) acc[a][f] = 0.0f;

        int k = slice;
        for (; k + 4 < nnb; k += 8) {
            const float2 mA = nb_meta[g][k];
            const float2 mB = nb_meta[g][k + 4];
            const float4 ccA = *reinterpret_cast<const float4*>(
                &s_sc1[__float_as_int(mA.y) + c2b]);
            const float4 ccB = *reinterpret_cast<const float4*>(
                &s_sc1[__float_as_int(mB.y) + c2b]);
            const float tA0 = mA.x - ccA.x, tA1 = mA.x - ccA.y;
            const float tA2 = mA.x - ccA.z, tA3 = mA.x - ccA.w;
            const float tB0 = mB.x - ccB.x, tB1 = mB.x - ccB.y;
            const float tB2 = mB.x - ccB.z, tB3 = mB.x - ccB.w;
            const float pA0 = ex2(-tA0 * tA0), pA1 = ex2(-tA1 * tA1);
            const float pA2 = ex2(-tA2 * tA2), pA3 = ex2(-tA3 * tA3);
            const float pB0 = ex2(-tB0 * tB0), pB1 = ex2(-tB1 * tB1);
            const float pB2 = ex2(-tB2 * tB2), pB3 = ex2(-tB3 * tB3);
            const float4 fA = nb_f4[g][k];
            const float4 fB = nb_f4[g][k + 4];
            acc[0][0] = fmaf(pA0, fA.x, acc[0][0]); acc[0][1] = fmaf(pA0, fA.y, acc[0][1]);
            acc[0][2] = fmaf(pA0, fA.z, acc[0][2]); acc[0][3] = fmaf(pA0, fA.w, acc[0][3]);
            acc[1][0] = fmaf(pA1, fA.x, acc[1][0]); acc[1][1] = fmaf(pA1, fA.y, acc[1][1]);
            acc[1][2] = fmaf(pA1, fA.z, acc[1][2]); acc[1][3] = fmaf(pA1, fA.w, acc[1][3]);
            acc[2][0] = fmaf(pA2, fA.x, acc[2][0]); acc[2][1] = fmaf(pA2, fA.y, acc[2][1]);
            acc[2][2] = fmaf(pA2, fA.z, acc[2][2]); acc[2][3] = fmaf(pA2, fA.w, acc[2][3]);
            acc[3][0] = fmaf(pA3, fA.x, acc[3][0]); acc[3][1] = fmaf(pA3, fA.y, acc[3][1]);
            acc[3][2] = fmaf(pA3, fA.z, acc[3][2]); acc[3][3] = fmaf(pA3, fA.w, acc[3][3]);
            acc[0][0] = fmaf(pB0, fB.x, acc[0][0]); acc[0][1] = fmaf(pB0, fB.y, acc[0][1]);
            acc[0][2] = fmaf(pB0, fB.z, acc[0][2]); acc[0][3] = fmaf(pB0, fB.w, acc[0][3]);
            acc[1][0] = fmaf(pB1, fB.x, acc[1][0]); acc[1][1] = fmaf(pB1, fB.y, acc[1][1]);
            acc[1][2] = fmaf(pB1, fB.z, acc[1][2]); acc[1][3] = fmaf(pB1, fB.w, acc[1][3]);
            acc[2][0] = fmaf(pB2, fB.x, acc[2][0]); acc[2][1] = fmaf(pB2, fB.y, acc[2][1]);
            acc[2][2] = fmaf(pB2, fB.z, acc[2][2]); acc[2][3] = fmaf(pB2, fB.w, acc[2][3]);
            acc[3][0] = fmaf(pB3, fB.x, acc[3][0]); acc[3][1] = fmaf(pB3, fB.y, acc[3][1]);
            acc[3][2] = fmaf(pB3, fB.z, acc[3][2]); acc[3][3] = fmaf(pB3, fB.w, acc[3][3]);
        }
        if (k < nnb) {
            const float2 m = nb_meta[g][k];
            const float4 cc = *reinterpret_cast<const float4*>(
                &s_sc1[__float_as_int(m.y) + c2b]);
            const float t0 = m.x - cc.x, t1 = m.x - cc.y;
            const float t2 = m.x - cc.z, t3 = m.x - cc.w;
            const float p0 = ex2(-t0 * t0), p1 = ex2(-t1 * t1);
            const float p2 = ex2(-t2 * t2), p3 = ex2(-t3 * t3);
            const float4 f = nb_f4[g][k];
            acc[0][0] = fmaf(p0, f.x, acc[0][0]); acc[0][1] = fmaf(p0, f.y, acc[0][1]);
            acc[0][2] = fmaf(p0, f.z, acc[0][2]); acc[0][3] = fmaf(p0, f.w, acc[0][3]);
            acc[1][0] = fmaf(p1, f.x, acc[1][0]); acc[1][1] = fmaf(p1, f.y, acc[1][1]);
            acc[1][2] = fmaf(p1, f.z, acc[1][2]); acc[1][3] = fmaf(p1, f.w, acc[1][3]);
            acc[2][0] = fmaf(p2, f.x, acc[2][0]); acc[2][1] = fmaf(p2, f.y, acc[2][1]);
            acc[2][2] = fmaf(p2, f.z, acc[2][2]); acc[2][3] = fmaf(p2, f.w, acc[2][3]);
            acc[3][0] = fmaf(p3, f.x, acc[3][0]); acc[3][1] = fmaf(p3, f.y, acc[3][1]);
            acc[3][2] = fmaf(p3, f.z, acc[3][2]); acc[3][3] = fmaf(p3, f.w, acc[3][3]);
        }
        #pragma unroll
        for (int a = 0; a < 4; a++)
            #pragma unroll
            for (int f = 0; f < 4; f++) {
                float v = acc[a][f];
                v += __shfl_xor_sync(0xffffffffu, v, 1);
                v += __shfl_xor_sync(0xffffffffu, v, 2);
                acc[a][f] = v;
            }
        if (slice == 0) {
            #pragma unroll
            for (int f = 0; f < 4; f++)
                *reinterpret_cast<float4*>(&LmT[g][f][c2b]) =
                    make_float4(acc[0][f], acc[1][f], acc[2][f], acc[3][f]);
        }
    }
    __syncthreads();

    // ---- Warp-per-atom epilogue: Gram -> rf -> scaled copy, all in-warp ----
    if (warp < GA) {
        const int g2   = warp;
        const int p    = lane >> 1;                  // 0..15
        const int part = lane & 1;
        const int pc   = (p < 10) ? p : 9;
        const float4* rf4 = reinterpret_cast<const float4*>(&LmT[g2][c_pf[pc]][part * 32]);
        const float4* rh4 = reinterpret_cast<const float4*>(&LmT[g2][c_ph[pc]][part * 32]);
        float s = 0.0f;
        #pragma unroll
        for (int q = 0; q < 8; q++) {
            const float4 x = rf4[q], y = rh4[q];
            s = fmaf(x.x, y.x, s); s = fmaf(x.y, y.y, s);
            s = fmaf(x.z, y.z, s); s = fmaf(x.w, y.w, s);
        }
        s += __shfl_xor_sync(0xffffffffu, s, 1);     // combine halves -> G_pc
        const float wq = (p < 10 && part == 0) ? c_pw[pc] : 0.0f;
        float tot = wq * s * s;
        tot += __shfl_xor_sync(0xffffffffu, tot, 1);
        tot += __shfl_xor_sync(0xffffffffu, tot, 2);
        tot += __shfl_xor_sync(0xffffffffu, tot, 4);
        tot += __shfl_xor_sync(0xffffffffu, tot, 8);
        tot += __shfl_xor_sync(0xffffffffu, tot, 16);
        const float rfv = rsqrtf(tot);
        const int base = lane * 8;
        const int ffb = base >> 6, ccb = base & 63;
        float4 v0 = *reinterpret_cast<const float4*>(&LmT[g2][ffb][ccb]);
        float4 v1 = *reinterpret_cast<const float4*>(&LmT[g2][ffb][ccb + 4]);
        v0.x *= rfv; v0.y *= rfv; v0.z *= rfv; v0.w *= rfv;
        v1.x *= rfv; v1.y *= rfv; v1.z *= rfv; v1.w *= rfv;
        *reinterpret_cast<float4*>(&LmTs[g2][ffb][ccb])     = v0;
        *reinterpret_cast<float4*>(&LmTs[g2][ffb][ccb + 4]) = v1;
    }
    __syncthreads();

    // ---- Phase 3: R = Lm (rf*Lm)^T; 8 float4 stores per thread per atom ----
    const int dd0 = (tid * 4) & 63;
    const int crw = tid >> 4;                        // 0..7
    #pragma unroll
    for (int g2 = 0; g2 < GA; g2++) {
        const float4 b0 = *reinterpret_cast<const float4*>(&LmTs[g2][0][dd0]);
        const float4 b1 = *reinterpret_cast<const float4*>(&LmTs[g2][1][dd0]);
        const float4 b2 = *reinterpret_cast<const float4*>(&LmTs[g2][2][dd0]);
        const float4 b3 = *reinterpret_cast<const float4*>(&LmTs[g2][3][dd0]);
        float* ob = out + ((size_t)(bidx * GA + g2) << 12);
        #pragma unroll
        for (int grp = 0; grp < 8; grp++) {
            const int c = grp * 8 + crw;
            const float a0 = LmT[g2][0][c], a1 = LmT[g2][1][c];
            const float a2 = LmT[g2][2][c], a3 = LmT[g2][3][c];
            float4 st;
            st.x = fmaf(a3, b3.x, fmaf(a2, b2.x, fmaf(a1, b1.x, a0 * b0.x)));
            st.y = fmaf(a3, b3.y, fmaf(a2, b2.y, fmaf(a1, b1.y, a0 * b0.y)));
            st.z = fmaf(a3, b3.z, fmaf(a2, b2.z, fmaf(a1, b1.z, a0 * b0.z)));
            st.w = fmaf(a3, b3.w, fmaf(a2, b2.w, fmaf(a1, b1.w, a0 * b0.w)));
            *reinterpret_cast<float4*>(ob + (grp << 9) + tid * 4) = st;
        }
    }
}

extern "C" void kernel_launch(void* const* d_in, const int* in_sizes, int n_in,
                              void* d_out, int out_size)
{
    // metadata order: boxs, numbers, coords, nuww0, sigmas0, centres0, nuww1, sigmas1, centres1
    const int*   numbers  = (const int*)  d_in[1];
    const float* coords   = (const float*)d_in[2];
    const float* nuww0    = (const float*)d_in[3];
    const float* sigmas0  = (const float*)d_in[4];
    const float* centres0 = (const float*)d_in[5];
    const float* nuww1    = (const float*)d_in[6];
    const float* sigmas1  = (const float*)d_in[7];
    const float* centres1 = (const float*)d_in[8];
    float* out = (float*)d_out;

    descriptor_kernel<<<(NBATCH * NATOM) / GA, NTHR>>>(
        numbers, coords, nuww0, sigmas0, centres0, nuww1, sigmas1, centres1, out);
}

// round 12
// speedup vs baseline: 1.3430x; 1.1609x over previous
#include <cuda_runtime.h>
#include <math.h>

#define NBATCH 4
#define NATOM  512
#define NSYM   4
#define NLAB   16
#define C1     32
#define C2     64
#define NTHR   128
#define GA     2          // atoms per CTA
#define MAXNB  96
#define C0P    36         // padded centres0 row (floats); 144B rows, 16B-aligned
#define C1P    68         // padded centres1 / LmT row (floats); 272B rows, 16B-aligned
#define SQK    1.2011224087864498f   // sqrt(log2(e))

__constant__ int   c_pf[16] = {0,0,0,0,1,1,1,2,2,3, 0,0,0,0,0,0};
__constant__ int   c_ph[16] = {0,1,2,3,1,2,3,2,3,3, 0,0,0,0,0,0};
__constant__ float c_pw[16] = {1,2,2,2,1,2,2,1,2,1, 0,0,0,0,0,0};

__device__ __forceinline__ float ex2(float x) {
    float r; asm("ex2.approx.ftz.f32 %0, %1;" : "=f"(r) : "f"(x)); return r;
}

__global__ __launch_bounds__(NTHR)
void descriptor_kernel(const int*   __restrict__ numbers,
                       const float* __restrict__ coords,
                       const float* __restrict__ nuww0,
                       const float* __restrict__ sigmas0,
                       const float* __restrict__ centres0,
                       const float* __restrict__ nuww1,
                       const float* __restrict__ sigmas1,
                       const float* __restrict__ centres1,
                       float*       __restrict__ out)
{
    __shared__ float4 s_pos[NATOM];                  // 8 KB
    __shared__ float  s_c0s[NLAB * C0P];             // 2.25 KB (c0*s0*SQK, padded)
    __shared__ float  s_sc1[NLAB * C1P];             // 4.25 KB (c1*s1*SQK, padded)
    __shared__ float  s_w0[NLAB], s_s0f[NLAB], s_w1[NLAB], s_s1f[NLAB];
    __shared__ float4 nb_f4[GA][MAXNB];              // 3 KB  (w1*fc, w1*gx, w1*gy, w1*gz)
    __shared__ float2 nb_meta[GA][MAXNB];            // 1.5 KB (rs*s1*SQK, row offset)
    __shared__ int    nb_j[GA][MAXNB];               // 0.75 KB (neighbor index only)
    __shared__ float  LmT [GA][4][C1P];              // 2.13 KB
    __shared__ float  LmTs[GA][4][C1P];              // 2.13 KB (rf-scaled copy)
    __shared__ int    s_wcnt[GA][4];

    const int tid  = threadIdx.x;
    const int bidx = blockIdx.x;
    const int b    = bidx >> 8;                      // 256 CTAs per batch
    const int li0  = (bidx & 255) * GA;
    const int lane = tid & 31;
    const int warp = tid >> 5;
    const int g    = tid >> 6;                       // atom served (0/1) in later phases
    const int t64  = tid & 63;

    // ---- cooperative loads + folded table pre-scaling (float4 paths) ----
    {
        const float* cb  = coords  + (size_t)b * NATOM * 3;
        const int*   nbp = numbers + (size_t)b * NATOM;
        for (int t = tid; t < NATOM; t += NTHR)
            s_pos[t] = make_float4(cb[t * 3 + 0], cb[t * 3 + 1], cb[t * 3 + 2],
                                   __int_as_float(nbp[t]));
        // centres0: 512 floats = 128 float4, one sweep
        {
            const float4 v = reinterpret_cast<const float4*>(centres0)[tid];
            const int lab = tid >> 3;                // 8 float4 per row
            const float s = sigmas0[lab] * SQK;
            *reinterpret_cast<float4*>(&s_c0s[lab * C0P + (tid & 7) * 4]) =
                make_float4(v.x * s, v.y * s, v.z * s, v.w * s);
        }
        // centres1: 1024 floats = 256 float4, two sweeps
        #pragma unroll
        for (int r = 0; r < 2; r++) {
            const int idx = tid + r * NTHR;
            const float4 v = reinterpret_cast<const float4*>(centres1)[idx];
            const int lab = idx >> 4;                // 16 float4 per row
            const float s = sigmas1[lab] * SQK;
            *reinterpret_cast<float4*>(&s_sc1[lab * C1P + (idx & 15) * 4]) =
                make_float4(v.x * s, v.y * s, v.z * s, v.w * s);
        }
        if (tid < NLAB) {
            s_w0[tid]  = nuww0[tid];  s_s0f[tid] = sigmas0[tid] * SQK;
            s_w1[tid]  = nuww1[tid];  s_s1f[tid] = sigmas1[tid] * SQK;
        }
    }
    __syncthreads();

    // ---- Phase 1a: shared-j test + index-only compaction ----
    {
        const float4 ci0 = s_pos[li0];
        const float4 ci1 = s_pos[li0 + 1];

        unsigned mk0[4], mk1[4];
        int cnt0 = 0, cnt1 = 0;
        #pragma unroll
        for (int c = 0; c < 4; c++) {
            const int j = warp * 128 + c * 32 + lane;
            const float4 p = s_pos[j];
            const float dx0 = p.x - ci0.x, dy0 = p.y - ci0.y, dz0 = p.z - ci0.z;
            const float dx1 = p.x - ci1.x, dy1 = p.y - ci1.y, dz1 = p.z - ci1.z;
            const float d20 = dx0 * dx0 + dy0 * dy0 + dz0 * dz0;
            const float d21 = dx1 * dx1 + dy1 * dy1 + dz1 * dz1;
            const bool f0 = (j != li0)     && (d20 <= 36.0f);
            const bool f1 = (j != li0 + 1) && (d21 <= 36.0f);
            mk0[c] = __ballot_sync(0xffffffffu, f0);
            mk1[c] = __ballot_sync(0xffffffffu, f1);
            cnt0 += __popc(mk0[c]);
            cnt1 += __popc(mk1[c]);
        }
        if (lane == 0) { s_wcnt[0][warp] = cnt0; s_wcnt[1][warp] = cnt1; }
        __syncthreads();

        int base0 = 0, base1 = 0;
        #pragma unroll
        for (int w = 0; w < 4; w++) {
            if (w < warp) { base0 += s_wcnt[0][w]; base1 += s_wcnt[1][w]; }
        }
        const unsigned ltmask = (1u << lane) - 1u;
        #pragma unroll
        for (int c = 0; c < 4; c++) {
            const int j = warp * 128 + c * 32 + lane;
            if ((mk0[c] >> lane) & 1u) {
                const int pos = base0 + __popc(mk0[c] & ltmask);
                if (pos < MAXNB) nb_j[0][pos] = j;
            }
            base0 += __popc(mk0[c]);
            if ((mk1[c] >> lane) & 1u) {
                const int pos = base1 + __popc(mk1[c] & ltmask);
                if (pos < MAXNB) nb_j[1][pos] = j;
            }
            base1 += __popc(mk1[c]);
        }
    }
    __syncthreads();

    const int nnb = min(s_wcnt[g][0] + s_wcnt[g][1] +
                        s_wcnt[g][2] + s_wcnt[g][3], MAXNB);

    // ---- Phase 1b: geometry + first RConv (4 thr/pair, 16 pairs/sweep) ----
    // All 4 threads of a pair compute the geometry redundantly (warp-converged);
    // sub==0 writes the per-neighbor feature vector (w1-folded) and meta.
    {
        const float4 ci = s_pos[li0 + g];
        const int zbase = __float_as_int(ci.w) * NSYM;
        const int sub  = t64 & 3;                    // channel group of 8
        const int slot = t64 >> 2;                   // 0..15
        const int nIter = (nnb + 15) >> 4;           // warp-uniform (same g per warp)
        for (int it = 0; it < nIter; it++) {
            const int p  = slot + (it << 4);
            const int pc = (p < nnb) ? p : (nnb - 1);
            const int j  = nb_j[g][pc];
            const float4 pj = s_pos[j];
            const float dx = pj.x - ci.x, dy = pj.y - ci.y, dz = pj.z - ci.z;
            const float d2 = dx * dx + dy * dy + dz * dz;
            const float rinv = (d2 > 0.0f) ? rsqrtf(d2) : 0.0f;
            const float d    = d2 * rinv;
            const float fc   = 0.5f * __cosf(d * 0.52359877559829887f) + 0.5f;
            const int   lab  = zbase + __float_as_int(pj.w);
            const float fcs  = fc * s_s0f[lab];
            const float4 cA = *reinterpret_cast<const float4*>(&s_c0s[lab * C0P + sub * 8]);
            const float4 cB = *reinterpret_cast<const float4*>(&s_c0s[lab * C0P + sub * 8 + 4]);
            const float a0 = fcs - cA.x, a1 = fcs - cA.y, a2 = fcs - cA.z, a3 = fcs - cA.w;
            const float a4 = fcs - cB.x, a5 = fcs - cB.y, a6 = fcs - cB.z, a7 = fcs - cB.w;
            float sum = ex2(-a0 * a0) + ex2(-a1 * a1) + ex2(-a2 * a2) + ex2(-a3 * a3)
                      + ex2(-a4 * a4) + ex2(-a5 * a5) + ex2(-a6 * a6) + ex2(-a7 * a7);
            sum += __shfl_xor_sync(0xffffffffu, sum, 1);
            sum += __shfl_xor_sync(0xffffffffu, sum, 2);
            if (sub == 0 && p < nnb) {
                const float w1 = s_w1[lab];
                const float rs = s_w0[lab] * sum;
                nb_meta[g][p] = make_float2(rs * s_s1f[lab],
                                            __int_as_float(lab * C1P));
                const float gg = rinv * fc * w1;
                nb_f4[g][p] = make_float4(fc * w1, dx * gg, dy * gg, dz * gg);
            }
        }
    }
    __syncthreads();

    // ---- Phase 2: second RConv + Lm. 4 c2 x 4 neighbor-slices, k-unrolled x2 ----
    {
        const int lw    = t64 >> 5;
        const int l5    = t64 & 31;
        const int grp   = l5 >> 2;
        const int slice = l5 & 3;
        const int c2b   = (lw * 8 + grp) * 4;

        float acc[4][4];
        #pragma unroll
        for (int a = 0; a < 4; a++)
            #pragma unroll
            for (int f = 0; f < 4; f++) acc[a][f] = 0.0f;

        int k = slice;
        for (; k + 4 < nnb; k += 8) {
            const float2 mA = nb_meta[g][k];
            const float2 mB = nb_meta[g][k + 4];
            const float4 ccA = *reinterpret_cast<const float4*>(
                &s_sc1[__float_as_int(mA.y) + c2b]);
            const float4 ccB = *reinterpret_cast<const float4*>(
                &s_sc1[__float_as_int(mB.y) + c2b]);
            const float tA0 = mA.x - ccA.x, tA1 = mA.x - ccA.y;
            const float tA2 = mA.x - ccA.z, tA3 = mA.x - ccA.w;
            const float tB0 = mB.x - ccB.x, tB1 = mB.x - ccB.y;
            const float tB2 = mB.x - ccB.z, tB3 = mB.x - ccB.w;
            const float pA0 = ex2(-tA0 * tA0), pA1 = ex2(-tA1 * tA1);
            const float pA2 = ex2(-tA2 * tA2), pA3 = ex2(-tA3 * tA3);
            const float pB0 = ex2(-tB0 * tB0), pB1 = ex2(-tB1 * tB1);
            const float pB2 = ex2(-tB2 * tB2), pB3 = ex2(-tB3 * tB3);
            const float4 fA = nb_f4[g][k];
            const float4 fB = nb_f4[g][k + 4];
            acc[0][0] = fmaf(pA0, fA.x, acc[0][0]); acc[0][1] = fmaf(pA0, fA.y, acc[0][1]);
            acc[0][2] = fmaf(pA0, fA.z, acc[0][2]); acc[0][3] = fmaf(pA0, fA.w, acc[0][3]);
            acc[1][0] = fmaf(pA1, fA.x, acc[1][0]); acc[1][1] = fmaf(pA1, fA.y, acc[1][1]);
            acc[1][2] = fmaf(pA1, fA.z, acc[1][2]); acc[1][3] = fmaf(pA1, fA.w, acc[1][3]);
            acc[2][0] = fmaf(pA2, fA.x, acc[2][0]); acc[2][1] = fmaf(pA2, fA.y, acc[2][1]);
            acc[2][2] = fmaf(pA2, fA.z, acc[2][2]); acc[2][3] = fmaf(pA2, fA.w, acc[2][3]);
            acc[3][0] = fmaf(pA3, fA.x, acc[3][0]); acc[3][1] = fmaf(pA3, fA.y, acc[3][1]);
            acc[3][2] = fmaf(pA3, fA.z, acc[3][2]); acc[3][3] = fmaf(pA3, fA.w, acc[3][3]);
            acc[0][0] = fmaf(pB0, fB.x, acc[0][0]); acc[0][1] = fmaf(pB0, fB.y, acc[0][1]);
            acc[0][2] = fmaf(pB0, fB.z, acc[0][2]); acc[0][3] = fmaf(pB0, fB.w, acc[0][3]);
            acc[1][0] = fmaf(pB1, fB.x, acc[1][0]); acc[1][1] = fmaf(pB1, fB.y, acc[1][1]);
            acc[1][2] = fmaf(pB1, fB.z, acc[1][2]); acc[1][3] = fmaf(pB1, fB.w, acc[1][3]);
            acc[2][0] = fmaf(pB2, fB.x, acc[2][0]); acc[2][1] = fmaf(pB2, fB.y, acc[2][1]);
            acc[2][2] = fmaf(pB2, fB.z, acc[2][2]); acc[2][3] = fmaf(pB2, fB.w, acc[2][3]);
            acc[3][0] = fmaf(pB3, fB.x, acc[3][0]); acc[3][1] = fmaf(pB3, fB.y, acc[3][1]);
            acc[3][2] = fmaf(pB3, fB.z, acc[3][2]); acc[3][3] = fmaf(pB3, fB.w, acc[3][3]);
        }
        if (k < nnb) {
            const float2 m = nb_meta[g][k];
            const float4 cc = *reinterpret_cast<const float4*>(
                &s_sc1[__float_as_int(m.y) + c2b]);
            const float t0 = m.x - cc.x, t1 = m.x - cc.y;
            const float t2 = m.x - cc.z, t3 = m.x - cc.w;
            const float p0 = ex2(-t0 * t0), p1 = ex2(-t1 * t1);
            const float p2 = ex2(-t2 * t2), p3 = ex2(-t3 * t3);
            const float4 f = nb_f4[g][k];
            acc[0][0] = fmaf(p0, f.x, acc[0][0]); acc[0][1] = fmaf(p0, f.y, acc[0][1]);
            acc[0][2] = fmaf(p0, f.z, acc[0][2]); acc[0][3] = fmaf(p0, f.w, acc[0][3]);
            acc[1][0] = fmaf(p1, f.x, acc[1][0]); acc[1][1] = fmaf(p1, f.y, acc[1][1]);
            acc[1][2] = fmaf(p1, f.z, acc[1][2]); acc[1][3] = fmaf(p1, f.w, acc[1][3]);
            acc[2][0] = fmaf(p2, f.x, acc[2][0]); acc[2][1] = fmaf(p2, f.y, acc[2][1]);
            acc[2][2] = fmaf(p2, f.z, acc[2][2]); acc[2][3] = fmaf(p2, f.w, acc[2][3]);
            acc[3][0] = fmaf(p3, f.x, acc[3][0]); acc[3][1] = fmaf(p3, f.y, acc[3][1]);
            acc[3][2] = fmaf(p3, f.z, acc[3][2]); acc[3][3] = fmaf(p3, f.w, acc[3][3]);
        }
        #pragma unroll
        for (int a = 0; a < 4; a++)
            #pragma unroll
            for (int f = 0; f < 4; f++) {
                float v = acc[a][f];
                v += __shfl_xor_sync(0xffffffffu, v, 1);
                v += __shfl_xor_sync(0xffffffffu, v, 2);
                acc[a][f] = v;
            }
        if (slice == 0) {
            #pragma unroll
            for (int f = 0; f < 4; f++)
                *reinterpret_cast<float4*>(&LmT[g][f][c2b]) =
                    make_float4(acc[0][f], acc[1][f], acc[2][f], acc[3][f]);
        }
    }
    __syncthreads();

    // ---- Warp-per-atom epilogue: Gram -> rf -> scaled copy, all in-warp ----
    if (warp < GA) {
        const int g2   = warp;
        const int p    = lane >> 1;                  // 0..15
        const int part = lane & 1;
        const int pc   = (p < 10) ? p : 9;
        const float4* rf4 = reinterpret_cast<const float4*>(&LmT[g2][c_pf[pc]][part * 32]);
        const float4* rh4 = reinterpret_cast<const float4*>(&LmT[g2][c_ph[pc]][part * 32]);
        float s = 0.0f;
        #pragma unroll
        for (int q = 0; q < 8; q++) {
            const float4 x = rf4[q], y = rh4[q];
            s = fmaf(x.x, y.x, s); s = fmaf(x.y, y.y, s);
            s = fmaf(x.z, y.z, s); s = fmaf(x.w, y.w, s);
        }
        s += __shfl_xor_sync(0xffffffffu, s, 1);     // combine halves -> G_pc
        const float wq = (p < 10 && part == 0) ? c_pw[pc] : 0.0f;
        float tot = wq * s * s;
        tot += __shfl_xor_sync(0xffffffffu, tot, 1);
        tot += __shfl_xor_sync(0xffffffffu, tot, 2);
        tot += __shfl_xor_sync(0xffffffffu, tot, 4);
        tot += __shfl_xor_sync(0xffffffffu, tot, 8);
        tot += __shfl_xor_sync(0xffffffffu, tot, 16);
        const float rfv = rsqrtf(tot);
        const int base = lane * 8;
        const int ffb = base >> 6, ccb = base & 63;
        float4 v0 = *reinterpret_cast<const float4*>(&LmT[g2][ffb][ccb]);
        float4 v1 = *reinterpret_cast<const float4*>(&LmT[g2][ffb][ccb + 4]);
        v0.x *= rfv; v0.y *= rfv; v0.z *= rfv; v0.w *= rfv;
        v1.x *= rfv; v1.y *= rfv; v1.z *= rfv; v1.w *= rfv;
        *reinterpret_cast<float4*>(&LmTs[g2][ffb][ccb])     = v0;
        *reinterpret_cast<float4*>(&LmTs[g2][ffb][ccb + 4]) = v1;
    }
    __syncthreads();

    // ---- Phase 3: R = Lm (rf*Lm)^T; 8 float4 stores per thread per atom ----
    const int dd0 = (tid * 4) & 63;
    const int crw = tid >> 4;                        // 0..7
    #pragma unroll
    for (int g2 = 0; g2 < GA; g2++) {
        const float4 b0 = *reinterpret_cast<const float4*>(&LmTs[g2][0][dd0]);
        const float4 b1 = *reinterpret_cast<const float4*>(&LmTs[g2][1][dd0]);
        const float4 b2 = *reinterpret_cast<const float4*>(&LmTs[g2][2][dd0]);
        const float4 b3 = *reinterpret_cast<const float4*>(&LmTs[g2][3][dd0]);
        float* ob = out + ((size_t)(bidx * GA + g2) << 12);
        #pragma unroll
        for (int grp = 0; grp < 8; grp++) {
            const int c = grp * 8 + crw;
            const float a0 = LmT[g2][0][c], a1 = LmT[g2][1][c];
            const float a2 = LmT[g2][2][c], a3 = LmT[g2][3][c];
            float4 st;
            st.x = fmaf(a3, b3.x, fmaf(a2, b2.x, fmaf(a1, b1.x, a0 * b0.x)));
            st.y = fmaf(a3, b3.y, fmaf(a2, b2.y, fmaf(a1, b1.y, a0 * b0.y)));
            st.z = fmaf(a3, b3.z, fmaf(a2, b2.z, fmaf(a1, b1.z, a0 * b0.z)));
            st.w = fmaf(a3, b3.w, fmaf(a2, b2.w, fmaf(a1, b1.w, a0 * b0.w)));
            *reinterpret_cast<float4*>(ob + (grp << 9) + tid * 4) = st;
        }
    }
}

extern "C" void kernel_launch(void* const* d_in, const int* in_sizes, int n_in,
                              void* d_out, int out_size)
{
    // metadata order: boxs, numbers, coords, nuww0, sigmas0, centres0, nuww1, sigmas1, centres1
    const int*   numbers  = (const int*)  d_in[1];
    const float* coords   = (const float*)d_in[2];
    const float* nuww0    = (const float*)d_in[3];
    const float* sigmas0  = (const float*)d_in[4];
    const float* centres0 = (const float*)d_in[5];
    const float* nuww1    = (const float*)d_in[6];
    const float* sigmas1  = (const float*)d_in[7];
    const float* centres1 = (const float*)d_in[8];
    float* out = (float*)d_out;

    descriptor_kernel<<<(NBATCH * NATOM) / GA, NTHR>>>(
        numbers, coords, nuww0, sigmas0, centres0, nuww1, sigmas1, centres1, out);
}

// round 13
// speedup vs baseline: 1.3535x; 1.0078x over previous
#include <cuda_runtime.h>
#include <math.h>

#define NBATCH 4
#define NATOM  512
#define NSYM   4
#define NLAB   16
#define C1     32
#define C2     64
#define NTHR   128
#define GA     2          // atoms per CTA
#define MAXNB  96
#define C0P    36         // padded centres0 row (floats); 144B rows, 16B-aligned
#define C1P    68         // padded centres1 / LmT row (floats); 272B rows, 16B-aligned
#define SQK    1.2011224087864498f   // sqrt(log2(e))

typedef unsigned long long u64;

__constant__ int   c_pf[16] = {0,0,0,0,1,1,1,2,2,3, 0,0,0,0,0,0};
__constant__ int   c_ph[16] = {0,1,2,3,1,2,3,2,3,3, 0,0,0,0,0,0};
__constant__ float c_pw[16] = {1,2,2,2,1,2,2,1,2,1, 0,0,0,0,0,0};

__device__ __forceinline__ float ex2(float x) {
    float r; asm("ex2.approx.ftz.f32 %0, %1;" : "=f"(r) : "f"(x)); return r;
}
__device__ __forceinline__ u64 pk2(float lo, float hi) {
    u64 r; asm("mov.b64 %0, {%1, %2};" : "=l"(r) : "f"(lo), "f"(hi)); return r;
}
__device__ __forceinline__ u64 fma2(u64 a, u64 b, u64 c) {
    u64 r; asm("fma.rn.f32x2 %0, %1, %2, %3;" : "=l"(r) : "l"(a), "l"(b), "l"(c)); return r;
}
__device__ __forceinline__ u64 mul2(u64 a, u64 b) {
    u64 r; asm("mul.rn.f32x2 %0, %1, %2;" : "=l"(r) : "l"(a), "l"(b)); return r;
}
__device__ __forceinline__ float2 upk2(u64 v) {
    float2 f; asm("mov.b64 {%0, %1}, %2;" : "=f"(f.x), "=f"(f.y) : "l"(v)); return f;
}

__global__ __launch_bounds__(NTHR)
void descriptor_kernel(const int*   __restrict__ numbers,
                       const float* __restrict__ coords,
                       const float* __restrict__ nuww0,
                       const float* __restrict__ sigmas0,
                       const float* __restrict__ centres0,
                       const float* __restrict__ nuww1,
                       const float* __restrict__ sigmas1,
                       const float* __restrict__ centres1,
                       float*       __restrict__ out)
{
    __shared__ float4 s_pos[NATOM];                  // 8 KB
    __shared__ float  s_c0s[NLAB * C0P];             // 2.25 KB (c0*s0*SQK, padded)
    __shared__ float  s_sc1[NLAB * C1P];             // 4.25 KB (c1*s1*SQK, padded)
    __shared__ float  s_w0[NLAB], s_s0f[NLAB], s_w1[NLAB], s_s1f[NLAB];
    __shared__ float4 nb_f4[GA][MAXNB];              // 3 KB  (w1*fc, w1*gx, w1*gy, w1*gz)
    __shared__ float2 nb_meta[GA][MAXNB];            // 1.5 KB (rs*s1*SQK, row offset)
    __shared__ int    nb_j[GA][MAXNB];               // 0.75 KB (neighbor index only)
    __shared__ float  LmT [GA][4][C1P];              // 2.13 KB
    __shared__ float  LmTs[GA][4][C1P];              // 2.13 KB (rf-scaled copy)
    __shared__ int    s_wcnt[GA][4];

    const int tid  = threadIdx.x;
    const int bidx = blockIdx.x;
    const int b    = bidx >> 8;                      // 256 CTAs per batch
    const int li0  = (bidx & 255) * GA;
    const int lane = tid & 31;
    const int warp = tid >> 5;
    const int g    = tid >> 6;                       // atom served (0/1) in later phases
    const int t64  = tid & 63;

    // ---- cooperative loads + folded table pre-scaling (float4 paths) ----
    {
        const float* cb  = coords  + (size_t)b * NATOM * 3;
        const int*   nbp = numbers + (size_t)b * NATOM;
        for (int t = tid; t < NATOM; t += NTHR)
            s_pos[t] = make_float4(cb[t * 3 + 0], cb[t * 3 + 1], cb[t * 3 + 2],
                                   __int_as_float(nbp[t]));
        // centres0: 512 floats = 128 float4, one sweep
        {
            const float4 v = reinterpret_cast<const float4*>(centres0)[tid];
            const int lab = tid >> 3;                // 8 float4 per row
            const float s = sigmas0[lab] * SQK;
            *reinterpret_cast<float4*>(&s_c0s[lab * C0P + (tid & 7) * 4]) =
                make_float4(v.x * s, v.y * s, v.z * s, v.w * s);
        }
        // centres1: 1024 floats = 256 float4, two sweeps
        #pragma unroll
        for (int r = 0; r < 2; r++) {
            const int idx = tid + r * NTHR;
            const float4 v = reinterpret_cast<const float4*>(centres1)[idx];
            const int lab = idx >> 4;                // 16 float4 per row
            const float s = sigmas1[lab] * SQK;
            *reinterpret_cast<float4*>(&s_sc1[lab * C1P + (idx & 15) * 4]) =
                make_float4(v.x * s, v.y * s, v.z * s, v.w * s);
        }
        if (tid < NLAB) {
            s_w0[tid]  = nuww0[tid];  s_s0f[tid] = sigmas0[tid] * SQK;
            s_w1[tid]  = nuww1[tid];  s_s1f[tid] = sigmas1[tid] * SQK;
        }
    }
    __syncthreads();

    // ---- Phase 1a: shared-j test + index-only compaction ----
    {
        const float4 ci0 = s_pos[li0];
        const float4 ci1 = s_pos[li0 + 1];

        unsigned mk0[4], mk1[4];
        int cnt0 = 0, cnt1 = 0;
        #pragma unroll
        for (int c = 0; c < 4; c++) {
            const int j = warp * 128 + c * 32 + lane;
            const float4 p = s_pos[j];
            const float dx0 = p.x - ci0.x, dy0 = p.y - ci0.y, dz0 = p.z - ci0.z;
            const float dx1 = p.x - ci1.x, dy1 = p.y - ci1.y, dz1 = p.z - ci1.z;
            const float d20 = dx0 * dx0 + dy0 * dy0 + dz0 * dz0;
            const float d21 = dx1 * dx1 + dy1 * dy1 + dz1 * dz1;
            const bool f0 = (j != li0)     && (d20 <= 36.0f);
            const bool f1 = (j != li0 + 1) && (d21 <= 36.0f);
            mk0[c] = __ballot_sync(0xffffffffu, f0);
            mk1[c] = __ballot_sync(0xffffffffu, f1);
            cnt0 += __popc(mk0[c]);
            cnt1 += __popc(mk1[c]);
        }
        if (lane == 0) { s_wcnt[0][warp] = cnt0; s_wcnt[1][warp] = cnt1; }
        __syncthreads();

        int base0 = 0, base1 = 0;
        #pragma unroll
        for (int w = 0; w < 4; w++) {
            if (w < warp) { base0 += s_wcnt[0][w]; base1 += s_wcnt[1][w]; }
        }
        const unsigned ltmask = (1u << lane) - 1u;
        #pragma unroll
        for (int c = 0; c < 4; c++) {
            const int j = warp * 128 + c * 32 + lane;
            if ((mk0[c] >> lane) & 1u) {
                const int pos = base0 + __popc(mk0[c] & ltmask);
                if (pos < MAXNB) nb_j[0][pos] = j;
            }
            base0 += __popc(mk0[c]);
            if ((mk1[c] >> lane) & 1u) {
                const int pos = base1 + __popc(mk1[c] & ltmask);
                if (pos < MAXNB) nb_j[1][pos] = j;
            }
            base1 += __popc(mk1[c]);
        }
    }
    __syncthreads();

    const int nnb = min(s_wcnt[g][0] + s_wcnt[g][1] +
                        s_wcnt[g][2] + s_wcnt[g][3], MAXNB);

    // ---- Phase 1b: geometry + first RConv (4 thr/pair, 16 pairs/sweep) ----
    {
        const float4 ci = s_pos[li0 + g];
        const int zbase = __float_as_int(ci.w) * NSYM;
        const int sub  = t64 & 3;                    // channel group of 8
        const int slot = t64 >> 2;                   // 0..15
        const int nIter = (nnb + 15) >> 4;           // warp-uniform (same g per warp)
        for (int it = 0; it < nIter; it++) {
            const int p  = slot + (it << 4);
            const int pc = (p < nnb) ? p : (nnb - 1);
            const int j  = nb_j[g][pc];
            const float4 pj = s_pos[j];
            const float dx = pj.x - ci.x, dy = pj.y - ci.y, dz = pj.z - ci.z;
            const float d2 = dx * dx + dy * dy + dz * dz;
            const float rinv = (d2 > 0.0f) ? rsqrtf(d2) : 0.0f;
            const float d    = d2 * rinv;
            const float fc   = 0.5f * __cosf(d * 0.52359877559829887f) + 0.5f;
            const int   lab  = zbase + __float_as_int(pj.w);
            const float fcs  = fc * s_s0f[lab];
            const float4 cA = *reinterpret_cast<const float4*>(&s_c0s[lab * C0P + sub * 8]);
            const float4 cB = *reinterpret_cast<const float4*>(&s_c0s[lab * C0P + sub * 8 + 4]);
            const float a0 = fcs - cA.x, a1 = fcs - cA.y, a2 = fcs - cA.z, a3 = fcs - cA.w;
            const float a4 = fcs - cB.x, a5 = fcs - cB.y, a6 = fcs - cB.z, a7 = fcs - cB.w;
            float sum = ex2(-a0 * a0) + ex2(-a1 * a1) + ex2(-a2 * a2) + ex2(-a3 * a3)
                      + ex2(-a4 * a4) + ex2(-a5 * a5) + ex2(-a6 * a6) + ex2(-a7 * a7);
            sum += __shfl_xor_sync(0xffffffffu, sum, 1);
            sum += __shfl_xor_sync(0xffffffffu, sum, 2);
            if (sub == 0 && p < nnb) {
                const float w1 = s_w1[lab];
                const float rs = s_w0[lab] * sum;
                nb_meta[g][p] = make_float2(rs * s_s1f[lab],
                                            __int_as_float(lab * C1P));
                const float gg = rinv * fc * w1;
                nb_f4[g][p] = make_float4(fc * w1, dx * gg, dy * gg, dz * gg);
            }
        }
    }
    __syncthreads();

    // ---- Phase 2: second RConv + Lm. Packed f32x2 accumulators, k-unrolled x2 ----
    {
        const int lw    = t64 >> 5;
        const int l5    = t64 & 31;
        const int grp   = l5 >> 2;
        const int slice = l5 & 3;
        const int c2b   = (lw * 8 + grp) * 4;

        u64 accp[4][2];                              // [c2i][f-pair: xy, zw]
        #pragma unroll
        for (int a = 0; a < 4; a++) { accp[a][0] = 0ull; accp[a][1] = 0ull; }

        int k = slice;
        for (; k + 4 < nnb; k += 8) {
            const float2 mA = nb_meta[g][k];
            const float2 mB = nb_meta[g][k + 4];
            const float4 ccA = *reinterpret_cast<const float4*>(
                &s_sc1[__float_as_int(mA.y) + c2b]);
            const float4 ccB = *reinterpret_cast<const float4*>(
                &s_sc1[__float_as_int(mB.y) + c2b]);
            const float tA0 = mA.x - ccA.x, tA1 = mA.x - ccA.y;
            const float tA2 = mA.x - ccA.z, tA3 = mA.x - ccA.w;
            const float tB0 = mB.x - ccB.x, tB1 = mB.x - ccB.y;
            const float tB2 = mB.x - ccB.z, tB3 = mB.x - ccB.w;
            const float pA0 = ex2(-tA0 * tA0), pA1 = ex2(-tA1 * tA1);
            const float pA2 = ex2(-tA2 * tA2), pA3 = ex2(-tA3 * tA3);
            const float pB0 = ex2(-tB0 * tB0), pB1 = ex2(-tB1 * tB1);
            const float pB2 = ex2(-tB2 * tB2), pB3 = ex2(-tB3 * tB3);
            const float4 fA = nb_f4[g][k];
            const float4 fB = nb_f4[g][k + 4];
            const u64 fAxy = pk2(fA.x, fA.y), fAzw = pk2(fA.z, fA.w);
            const u64 fBxy = pk2(fB.x, fB.y), fBzw = pk2(fB.z, fB.w);
            const u64 qA0 = pk2(pA0, pA0), qA1 = pk2(pA1, pA1);
            const u64 qA2 = pk2(pA2, pA2), qA3 = pk2(pA3, pA3);
            const u64 qB0 = pk2(pB0, pB0), qB1 = pk2(pB1, pB1);
            const u64 qB2 = pk2(pB2, pB2), qB3 = pk2(pB3, pB3);
            accp[0][0] = fma2(qA0, fAxy, accp[0][0]); accp[0][1] = fma2(qA0, fAzw, accp[0][1]);
            accp[1][0] = fma2(qA1, fAxy, accp[1][0]); accp[1][1] = fma2(qA1, fAzw, accp[1][1]);
            accp[2][0] = fma2(qA2, fAxy, accp[2][0]); accp[2][1] = fma2(qA2, fAzw, accp[2][1]);
            accp[3][0] = fma2(qA3, fAxy, accp[3][0]); accp[3][1] = fma2(qA3, fAzw, accp[3][1]);
            accp[0][0] = fma2(qB0, fBxy, accp[0][0]); accp[0][1] = fma2(qB0, fBzw, accp[0][1]);
            accp[1][0] = fma2(qB1, fBxy, accp[1][0]); accp[1][1] = fma2(qB1, fBzw, accp[1][1]);
            accp[2][0] = fma2(qB2, fBxy, accp[2][0]); accp[2][1] = fma2(qB2, fBzw, accp[2][1]);
            accp[3][0] = fma2(qB3, fBxy, accp[3][0]); accp[3][1] = fma2(qB3, fBzw, accp[3][1]);
        }
        if (k < nnb) {
            const float2 m = nb_meta[g][k];
            const float4 cc = *reinterpret_cast<const float4*>(
                &s_sc1[__float_as_int(m.y) + c2b]);
            const float t0 = m.x - cc.x, t1 = m.x - cc.y;
            const float t2 = m.x - cc.z, t3 = m.x - cc.w;
            const float p0 = ex2(-t0 * t0), p1 = ex2(-t1 * t1);
            const float p2 = ex2(-t2 * t2), p3 = ex2(-t3 * t3);
            const float4 f = nb_f4[g][k];
            const u64 fxy = pk2(f.x, f.y), fzw = pk2(f.z, f.w);
            const u64 q0 = pk2(p0, p0), q1 = pk2(p1, p1);
            const u64 q2 = pk2(p2, p2), q3 = pk2(p3, p3);
            accp[0][0] = fma2(q0, fxy, accp[0][0]); accp[0][1] = fma2(q0, fzw, accp[0][1]);
            accp[1][0] = fma2(q1, fxy, accp[1][0]); accp[1][1] = fma2(q1, fzw, accp[1][1]);
            accp[2][0] = fma2(q2, fxy, accp[2][0]); accp[2][1] = fma2(q2, fzw, accp[2][1]);
            accp[3][0] = fma2(q3, fxy, accp[3][0]); accp[3][1] = fma2(q3, fzw, accp[3][1]);
        }
        // unpack, then reduce across the 4 slices (lanes xor 1, 2)
        float accs[4][4];
        #pragma unroll
        for (int a = 0; a < 4; a++) {
            const float2 u0 = upk2(accp[a][0]);
            const float2 u1 = upk2(accp[a][1]);
            accs[a][0] = u0.x; accs[a][1] = u0.y;
            accs[a][2] = u1.x; accs[a][3] = u1.y;
        }
        #pragma unroll
        for (int a = 0; a < 4; a++)
            #pragma unroll
            for (int f = 0; f < 4; f++) {
                float v = accs[a][f];
                v += __shfl_xor_sync(0xffffffffu, v, 1);
                v += __shfl_xor_sync(0xffffffffu, v, 2);
                accs[a][f] = v;
            }
        if (slice == 0) {
            #pragma unroll
            for (int f = 0; f < 4; f++)
                *reinterpret_cast<float4*>(&LmT[g][f][c2b]) =
                    make_float4(accs[0][f], accs[1][f], accs[2][f], accs[3][f]);
        }
    }
    __syncthreads();

    // ---- Warp-per-atom epilogue: Gram -> rf -> scaled copy, all in-warp ----
    if (warp < GA) {
        const int g2   = warp;
        const int p    = lane >> 1;                  // 0..15
        const int part = lane & 1;
        const int pc   = (p < 10) ? p : 9;
        const float4* rf4 = reinterpret_cast<const float4*>(&LmT[g2][c_pf[pc]][part * 32]);
        const float4* rh4 = reinterpret_cast<const float4*>(&LmT[g2][c_ph[pc]][part * 32]);
        float s = 0.0f;
        #pragma unroll
        for (int q = 0; q < 8; q++) {
            const float4 x = rf4[q], y = rh4[q];
            s = fmaf(x.x, y.x, s); s = fmaf(x.y, y.y, s);
            s = fmaf(x.z, y.z, s); s = fmaf(x.w, y.w, s);
        }
        s += __shfl_xor_sync(0xffffffffu, s, 1);     // combine halves -> G_pc
        const float wq = (p < 10 && part == 0) ? c_pw[pc] : 0.0f;
        float tot = wq * s * s;
        tot += __shfl_xor_sync(0xffffffffu, tot, 1);
        tot += __shfl_xor_sync(0xffffffffu, tot, 2);
        tot += __shfl_xor_sync(0xffffffffu, tot, 4);
        tot += __shfl_xor_sync(0xffffffffu, tot, 8);
        tot += __shfl_xor_sync(0xffffffffu, tot, 16);
        const float rfv = rsqrtf(tot);
        const int base = lane * 8;
        const int ffb = base >> 6, ccb = base & 63;
        float4 v0 = *reinterpret_cast<const float4*>(&LmT[g2][ffb][ccb]);
        float4 v1 = *reinterpret_cast<const float4*>(&LmT[g2][ffb][ccb + 4]);
        v0.x *= rfv; v0.y *= rfv; v0.z *= rfv; v0.w *= rfv;
        v1.x *= rfv; v1.y *= rfv; v1.z *= rfv; v1.w *= rfv;
        *reinterpret_cast<float4*>(&LmTs[g2][ffb][ccb])     = v0;
        *reinterpret_cast<float4*>(&LmTs[g2][ffb][ccb + 4]) = v1;
    }
    __syncthreads();

    // ---- Phase 3: R = Lm (rf*Lm)^T with packed f32x2 FMA + v2.b64 stores ----
    const int dd0 = (tid * 4) & 63;
    const int crw = tid >> 4;                        // 0..7
    #pragma unroll
    for (int g2 = 0; g2 < GA; g2++) {
        const float4 b0 = *reinterpret_cast<const float4*>(&LmTs[g2][0][dd0]);
        const float4 b1 = *reinterpret_cast<const float4*>(&LmTs[g2][1][dd0]);
        const float4 b2 = *reinterpret_cast<const float4*>(&LmTs[g2][2][dd0]);
        const float4 b3 = *reinterpret_cast<const float4*>(&LmTs[g2][3][dd0]);
        const u64 b0xy = pk2(b0.x, b0.y), b0zw = pk2(b0.z, b0.w);
        const u64 b1xy = pk2(b1.x, b1.y), b1zw = pk2(b1.z, b1.w);
        const u64 b2xy = pk2(b2.x, b2.y), b2zw = pk2(b2.z, b2.w);
        const u64 b3xy = pk2(b3.x, b3.y), b3zw = pk2(b3.z, b3.w);
        float* ob = out + ((size_t)(bidx * GA + g2) << 12);
        #pragma unroll
        for (int grp = 0; grp < 8; grp++) {
            const int c = grp * 8 + crw;
            const u64 pa0 = pk2(LmT[g2][0][c], LmT[g2][0][c]);
            const u64 pa1 = pk2(LmT[g2][1][c], LmT[g2][1][c]);
            const u64 pa2 = pk2(LmT[g2][2][c], LmT[g2][2][c]);
            const u64 pa3 = pk2(LmT[g2][3][c], LmT[g2][3][c]);
            const u64 sxy = fma2(pa3, b3xy, fma2(pa2, b2xy, fma2(pa1, b1xy, mul2(pa0, b0xy))));
            const u64 szw = fma2(pa3, b3zw, fma2(pa2, b2zw, fma2(pa1, b1zw, mul2(pa0, b0zw))));
            float* ptr = ob + (grp << 9) + tid * 4;
            asm volatile("st.global.v2.b64 [%0], {%1, %2};"
                         :: "l"(ptr), "l"(sxy), "l"(szw) : "memory");
        }
    }
}

extern "C" void kernel_launch(void* const* d_in, const int* in_sizes, int n_in,
                              void* d_out, int out_size)
{
    // metadata order: boxs, numbers, coords, nuww0, sigmas0, centres0, nuww1, sigmas1, centres1
    const int*   numbers  = (const int*)  d_in[1];
    const float* coords   = (const float*)d_in[2];
    const float* nuww0    = (const float*)d_in[3];
    const float* sigmas0  = (const float*)d_in[4];
    const float* centres0 = (const float*)d_in[5];
    const float* nuww1    = (const float*)d_in[6];
    const float* sigmas1  = (const float*)d_in[7];
    const float* centres1 = (const float*)d_in[8];
    float* out = (float*)d_out;

    descriptor_kernel<<<(NBATCH * NATOM) / GA, NTHR>>>(
        numbers, coords, nuww0, sigmas0, centres0, nuww1, sigmas1, centres1, out);
}